// round 2
// baseline (speedup 1.0000x reference)
#include <cuda_runtime.h>

#define Bdim 32
#define Tdim 2048
#define Hdim 1024
#define Udim 1024
#define NCHUNK 32          // chunks per batch row
#define CHUNK 64           // Tdim / NCHUNK timesteps per CTA
#define TG 8               // timesteps per inner group (register-resident)
#define NEGBIG (-1e9f)

// Scratch (no allocs allowed)
__device__ float g_v[Bdim * Hdim];                      // projected Wa @ dec
__device__ float g_pm[Bdim * NCHUNK];                   // per-chunk running max
__device__ float g_pl[Bdim * NCHUNK];                   // per-chunk denom
__device__ float g_pctx[(size_t)Bdim * NCHUNK * Hdim];  // 4 MB ctx partials
__device__ unsigned char g_mask8[Bdim * Tdim];          // canonicalized mask

// ---------------------------------------------------------------------------
// Kernel 0: sniff the mask storage format and canonicalize to uint8.
//   The harness may pass the bool mask as uint8 (1B), int32 (4B, values 0/1),
//   or float32 (0.0/1.0). Distinguish by scanning the first 16384 32-bit words
//   (safe for all three: 16384*4 = 65536 B = exact uint8 buffer size).
// ---------------------------------------------------------------------------
__global__ __launch_bounds__(256) void mask_prep(const void* __restrict__ mraw) {
    __shared__ int s_not_int, s_not_flt;
    if (threadIdx.x == 0) { s_not_int = 0; s_not_flt = 0; }
    __syncthreads();

    const unsigned int* w = (const unsigned int*)mraw;
    int bad_i = 0, bad_f = 0;
    for (int i = threadIdx.x; i < (Bdim * Tdim) / 4; i += 256) {
        unsigned int x = w[i];
        if (x > 1u) bad_i = 1;
        if (x != 0u && x != 0x3f800000u) bad_f = 1;
    }
    if (bad_i) atomicOr(&s_not_int, 1);
    if (bad_f) atomicOr(&s_not_flt, 1);
    __syncthreads();

    // mode: 0 = int32, 1 = float32, 2 = uint8
    const int mode = (!s_not_int) ? 0 : ((!s_not_flt) ? 1 : 2);

    if (mode == 0) {
        const int* m = (const int*)mraw;
        for (int i = threadIdx.x; i < Bdim * Tdim; i += 256)
            g_mask8[i] = (m[i] != 0);
    } else if (mode == 1) {
        const float* m = (const float*)mraw;
        for (int i = threadIdx.x; i < Bdim * Tdim; i += 256)
            g_mask8[i] = (m[i] != 0.f);
    } else {
        const unsigned char* m = (const unsigned char*)mraw;
        for (int i = threadIdx.x; i < Bdim * Tdim; i += 256)
            g_mask8[i] = (m[i] != 0);
    }
}

// ---------------------------------------------------------------------------
// Kernel 1: v[b,h] = sum_u Wa[h,u] * dec_ht[b,u]
// One block per h; Wa row staged in smem once, reused for all 32 batch rows.
// ---------------------------------------------------------------------------
__global__ __launch_bounds__(256) void proj_kernel(const float* __restrict__ Wa,
                                                   const float* __restrict__ dec) {
    int h = blockIdx.x;
    __shared__ __align__(16) float w[Udim];
    for (int i = threadIdx.x; i < Udim; i += 256)
        w[i] = Wa[(size_t)h * Udim + i];
    __syncthreads();

    int warp = threadIdx.x >> 5;
    int lane = threadIdx.x & 31;
    for (int b = warp; b < Bdim; b += 8) {
        const float* d = dec + (size_t)b * Udim;
        float s = 0.f;
        #pragma unroll
        for (int k = 0; k < Udim / (32 * 4); ++k) {
            int u = (k * 32 + lane) * 4;
            float4 ww = *reinterpret_cast<const float4*>(&w[u]);
            float4 dd = *reinterpret_cast<const float4*>(&d[u]);
            s += ww.x * dd.x + ww.y * dd.y + ww.z * dd.z + ww.w * dd.w;
        }
        #pragma unroll
        for (int o = 16; o; o >>= 1) s += __shfl_xor_sync(0xffffffffu, s, o);
        if (lane == 0) g_v[b * Hdim + h] = s;
    }
}

// ---------------------------------------------------------------------------
// Kernel 2: fused score + online softmax + context partial, one pass over enc.
// Grid (NCHUNK, Bdim); 256 threads; each thread owns 4 h-columns (float4).
// ---------------------------------------------------------------------------
__global__ __launch_bounds__(256) void attn_main(const float* __restrict__ enc) {
    const int b    = blockIdx.y;
    const int c    = blockIdx.x;
    const int tid  = threadIdx.x;
    const int warp = tid >> 5;
    const int lane = tid & 31;
    const int h4   = tid * 4;

    float4 v4  = *reinterpret_cast<const float4*>(&g_v[b * Hdim + h4]);
    float4 ctx = make_float4(0.f, 0.f, 0.f, 0.f);
    float  m   = -1e30f;
    float  l   = 0.f;

    __shared__ __align__(16) float red[2][TG][8];   // [buf][timestep][warp]

    const float* encb = enc + (size_t)b * Tdim * Hdim;
    const int t0base  = c * CHUNK;

    for (int g = 0; g < CHUNK / TG; ++g) {
        const int t0  = t0base + g * TG;
        const int buf = g & 1;

        float4 e[TG];
        unsigned char mk[TG];
        #pragma unroll
        for (int j = 0; j < TG; ++j)
            e[j] = *reinterpret_cast<const float4*>(&encb[(size_t)(t0 + j) * Hdim + h4]);
        #pragma unroll
        for (int j = 0; j < TG; ++j)
            mk[j] = g_mask8[b * Tdim + t0 + j];

        #pragma unroll
        for (int j = 0; j < TG; ++j) {
            if (!mk[j]) e[j] = make_float4(0.f, 0.f, 0.f, 0.f);
            float p = e[j].x * v4.x + e[j].y * v4.y + e[j].z * v4.z + e[j].w * v4.w;
            #pragma unroll
            for (int o = 16; o; o >>= 1) p += __shfl_xor_sync(0xffffffffu, p, o);
            if (lane == 0) red[buf][j][warp] = p;
        }
        __syncthreads();

        float sc[TG];
        #pragma unroll
        for (int j = 0; j < TG; ++j) {
            float4 a  = *reinterpret_cast<const float4*>(&red[buf][j][0]);
            float4 bb = *reinterpret_cast<const float4*>(&red[buf][j][4]);
            sc[j] = a.x + a.y + a.z + a.w + bb.x + bb.y + bb.z + bb.w;
            if (!mk[j]) sc[j] = NEGBIG;
        }

        float gmax = sc[0];
        #pragma unroll
        for (int j = 1; j < TG; ++j) gmax = fmaxf(gmax, sc[j]);
        float mnew  = fmaxf(m, gmax);
        float scale = __expf(m - mnew);
        ctx.x *= scale; ctx.y *= scale; ctx.z *= scale; ctx.w *= scale;
        l *= scale;
        #pragma unroll
        for (int j = 0; j < TG; ++j) {
            float p = __expf(sc[j] - mnew);
            l += p;
            ctx.x += p * e[j].x;
            ctx.y += p * e[j].y;
            ctx.z += p * e[j].z;
            ctx.w += p * e[j].w;
        }
        m = mnew;
    }

    const int idx = b * NCHUNK + c;
    if (tid == 0) { g_pm[idx] = m; g_pl[idx] = l; }
    *reinterpret_cast<float4*>(&g_pctx[(size_t)idx * Hdim + h4]) = ctx;
}

// ---------------------------------------------------------------------------
// Kernel 3: merge NCHUNK partials per batch row -> context[b,h].
// ---------------------------------------------------------------------------
__global__ __launch_bounds__(256) void attn_reduce(float* __restrict__ out) {
    const int b  = blockIdx.x;
    const int h4 = threadIdx.x * 4;

    float M = -1e30f;
    #pragma unroll 4
    for (int c = 0; c < NCHUNK; ++c) M = fmaxf(M, g_pm[b * NCHUNK + c]);

    float L = 0.f;
    float4 acc = make_float4(0.f, 0.f, 0.f, 0.f);
    #pragma unroll 4
    for (int c = 0; c < NCHUNK; ++c) {
        const int idx = b * NCHUNK + c;
        float w = __expf(g_pm[idx] - M);
        L += g_pl[idx] * w;
        float4 p = *reinterpret_cast<const float4*>(&g_pctx[(size_t)idx * Hdim + h4]);
        acc.x += w * p.x; acc.y += w * p.y; acc.z += w * p.z; acc.w += w * p.w;
    }
    float inv = 1.f / L;
    float4 o = make_float4(acc.x * inv, acc.y * inv, acc.z * inv, acc.w * inv);
    *reinterpret_cast<float4*>(&out[b * Hdim + h4]) = o;
}

// ---------------------------------------------------------------------------
extern "C" void kernel_launch(void* const* d_in, const int* in_sizes, int n_in,
                              void* d_out, int out_size) {
    // Bind inputs by element count (all four are distinct) — robust to order.
    const float* enc  = nullptr;   // 32*2048*1024 = 67108864
    const float* dec  = nullptr;   // 32*1024     = 32768
    const void*  mask = nullptr;   // 32*2048     = 65536
    const float* Wa   = nullptr;   // 1024*1024   = 1048576
    for (int i = 0; i < n_in; ++i) {
        switch (in_sizes[i]) {
            case 67108864: enc  = (const float*)d_in[i]; break;
            case 32768:    dec  = (const float*)d_in[i]; break;
            case 65536:    mask = d_in[i];               break;
            case 1048576:  Wa   = (const float*)d_in[i]; break;
        }
    }
    float* out = (float*)d_out;

    mask_prep<<<1, 256>>>(mask);
    proj_kernel<<<Hdim, 256>>>(Wa, dec);
    dim3 grid(NCHUNK, Bdim);
    attn_main<<<grid, 256>>>(enc);
    attn_reduce<<<Bdim, 256>>>(out);
}

// round 3
// speedup vs baseline: 1.1319x; 1.1319x over previous
#include <cuda_runtime.h>

#define Bdim 32
#define Tdim 2048
#define Hdim 1024
#define Udim 1024
#define NCHUNK 32          // chunks per batch row
#define CHUNK 64           // Tdim / NCHUNK timesteps per CTA
#define NWARP 8
#define TPW (CHUNK / NWARP)   // 8 timesteps per warp
#define NEGBIG (-1e9f)

// Scratch (no allocs allowed)
__device__ float g_v[Bdim * Hdim];                      // Wa @ dec
__device__ float g_pm[Bdim * NCHUNK];
__device__ float g_pl[Bdim * NCHUNK];
__device__ float g_pctx[(size_t)Bdim * NCHUNK * Hdim];  // 4 MB ctx partials
__device__ int   g_mode;                                // 0=int32 1=float32 2=uint8

// ---------------------------------------------------------------------------
// Kernel 0: detect mask storage format (writes g_mode only).
// Scans first 16384 32-bit words — safe for uint8(64KB)/int32/float32 buffers.
// ---------------------------------------------------------------------------
__global__ __launch_bounds__(1024) void mask_detect(const unsigned int* __restrict__ w) {
    __shared__ int s_not_int, s_not_flt;
    if (threadIdx.x == 0) { s_not_int = 0; s_not_flt = 0; }
    __syncthreads();
    int bad_i = 0, bad_f = 0;
    #pragma unroll 4
    for (int i = threadIdx.x; i < (Bdim * Tdim) / 4; i += 1024) {
        unsigned int x = w[i];
        if (x > 1u) bad_i = 1;
        if (x != 0u && x != 0x3f800000u) bad_f = 1;
    }
    if (bad_i) atomicOr(&s_not_int, 1);
    if (bad_f) atomicOr(&s_not_flt, 1);
    __syncthreads();
    if (threadIdx.x == 0)
        g_mode = (!s_not_int) ? 0 : ((!s_not_flt) ? 1 : 2);
}

// ---------------------------------------------------------------------------
// Kernel 1: v[b,h] = sum_u Wa[h,u] * dec_ht[b,u]
// ---------------------------------------------------------------------------
__global__ __launch_bounds__(256) void proj_kernel(const float* __restrict__ Wa,
                                                   const float* __restrict__ dec) {
    int h = blockIdx.x;
    __shared__ __align__(16) float w[Udim];
    for (int i = threadIdx.x; i < Udim; i += 256)
        w[i] = Wa[(size_t)h * Udim + i];
    __syncthreads();

    int warp = threadIdx.x >> 5;
    int lane = threadIdx.x & 31;
    for (int b = warp; b < Bdim; b += 8) {
        const float* d = dec + (size_t)b * Udim;
        float s = 0.f;
        #pragma unroll
        for (int k = 0; k < Udim / (32 * 4); ++k) {
            int u = (k * 32 + lane) * 4;
            float4 ww = *reinterpret_cast<const float4*>(&w[u]);
            float4 dd = *reinterpret_cast<const float4*>(&d[u]);
            s += ww.x * dd.x + ww.y * dd.y + ww.z * dd.z + ww.w * dd.w;
        }
        #pragma unroll
        for (int o = 16; o; o >>= 1) s += __shfl_xor_sync(0xffffffffu, s, o);
        if (lane == 0) g_v[b * Hdim + h] = s;
    }
}

// ---------------------------------------------------------------------------
// Kernel 2: warp-per-timestep fused pass. No block syncs in the main loop.
// Each warp processes TPW=8 full enc rows (1024 h, 8x float4 per lane),
// in-warp score reduce, per-warp online softmax + ctx, end merge in smem.
// ---------------------------------------------------------------------------
__global__ __launch_bounds__(256, 2) void attn_main(const float* __restrict__ enc,
                                                    const void* __restrict__ mraw) {
    const int b    = blockIdx.y;
    const int c    = blockIdx.x;
    const int tid  = threadIdx.x;
    const int w    = tid >> 5;
    const int lane = tid & 31;

    __shared__ __align__(16) float sv[Hdim];          // 4 KB
    __shared__ __align__(16) float sctx[NWARP][Hdim]; // 32 KB
    __shared__ float sm[NWARP], sl[NWARP];

    for (int i = tid; i < Hdim; i += 256) sv[i] = g_v[b * Hdim + i];
    __syncthreads();

    const int  mode  = g_mode;
    const int  tbase = c * CHUNK + w * TPW;               // this warp's first t
    const float* rowp = enc + (size_t)b * Tdim * Hdim + (size_t)tbase * Hdim;
    const int  mbase = b * Tdim + tbase;

    float4 ctx[8];
    #pragma unroll
    for (int k = 0; k < 8; ++k) ctx[k] = make_float4(0.f, 0.f, 0.f, 0.f);
    float m = -1e30f, l = 0.f;

    // prefetch row 0
    float4 cur[8];
    #pragma unroll
    for (int k = 0; k < 8; ++k)
        cur[k] = *reinterpret_cast<const float4*>(rowp + k * 128 + lane * 4);

    #pragma unroll
    for (int j = 0; j < TPW; ++j) {
        float4 nxt[8];
        if (j + 1 < TPW) {
            const float* np = rowp + (size_t)(j + 1) * Hdim;
            #pragma unroll
            for (int k = 0; k < 8; ++k)
                nxt[k] = *reinterpret_cast<const float4*>(np + k * 128 + lane * 4);
        }

        // mask value for this timestep (uniform across warp)
        float mkf;
        if (mode == 0)      mkf = ((const int*)mraw)[mbase + j]          ? 1.f : 0.f;
        else if (mode == 1) mkf = (((const float*)mraw)[mbase + j] != 0.f) ? 1.f : 0.f;
        else                mkf = ((const unsigned char*)mraw)[mbase + j] ? 1.f : 0.f;

        // zero masked enc (matches reference enc*mask, incl. all-masked case)
        #pragma unroll
        for (int k = 0; k < 8; ++k) {
            cur[k].x *= mkf; cur[k].y *= mkf; cur[k].z *= mkf; cur[k].w *= mkf;
        }

        // dot(enc_row, v) — in-warp only
        float s = 0.f;
        #pragma unroll
        for (int k = 0; k < 8; ++k) {
            float4 vv = *reinterpret_cast<const float4*>(&sv[k * 128 + lane * 4]);
            s += cur[k].x * vv.x + cur[k].y * vv.y + cur[k].z * vv.z + cur[k].w * vv.w;
        }
        #pragma unroll
        for (int o = 16; o; o >>= 1) s += __shfl_xor_sync(0xffffffffu, s, o);
        if (mkf == 0.f) s = NEGBIG;

        // online softmax update (warp-uniform values)
        float mnew = fmaxf(m, s);
        if (mnew != m) {
            float scale = __expf(m - mnew);
            l *= scale;
            #pragma unroll
            for (int k = 0; k < 8; ++k) {
                ctx[k].x *= scale; ctx[k].y *= scale;
                ctx[k].z *= scale; ctx[k].w *= scale;
            }
            m = mnew;
        }
        float p = __expf(s - m);
        l += p;
        #pragma unroll
        for (int k = 0; k < 8; ++k) {
            ctx[k].x += p * cur[k].x; ctx[k].y += p * cur[k].y;
            ctx[k].z += p * cur[k].z; ctx[k].w += p * cur[k].w;
        }

        if (j + 1 < TPW) {
            #pragma unroll
            for (int k = 0; k < 8; ++k) cur[k] = nxt[k];
        }
    }

    // ---- merge 8 warps ----
    if (lane == 0) { sm[w] = m; sl[w] = l; }
    #pragma unroll
    for (int k = 0; k < 8; ++k)
        *reinterpret_cast<float4*>(&sctx[w][k * 128 + lane * 4]) = ctx[k];
    __syncthreads();

    float M = -1e30f;
    #pragma unroll
    for (int ww = 0; ww < NWARP; ++ww) M = fmaxf(M, sm[ww]);
    float wsc[NWARP];
    float L = 0.f;
    #pragma unroll
    for (int ww = 0; ww < NWARP; ++ww) {
        wsc[ww] = __expf(sm[ww] - M);
        L += sl[ww] * wsc[ww];
    }

    const int h4 = tid * 4;
    float4 acc = make_float4(0.f, 0.f, 0.f, 0.f);
    #pragma unroll
    for (int ww = 0; ww < NWARP; ++ww) {
        float4 pc = *reinterpret_cast<const float4*>(&sctx[ww][h4]);
        acc.x += wsc[ww] * pc.x; acc.y += wsc[ww] * pc.y;
        acc.z += wsc[ww] * pc.z; acc.w += wsc[ww] * pc.w;
    }

    const int idx = b * NCHUNK + c;
    if (tid == 0) { g_pm[idx] = M; g_pl[idx] = L; }
    *reinterpret_cast<float4*>(&g_pctx[(size_t)idx * Hdim + h4]) = acc;
}

// ---------------------------------------------------------------------------
// Kernel 3: merge NCHUNK partials -> context.  grid (Bdim, 4), 64 threads,
// each thread owns one float4 column group; M/L recomputed per block (cheap).
// ---------------------------------------------------------------------------
__global__ __launch_bounds__(64) void attn_reduce(float* __restrict__ out) {
    const int b  = blockIdx.x;
    const int h4 = (blockIdx.y * 64 + threadIdx.x) * 4;

    float M = -1e30f;
    #pragma unroll 8
    for (int c = 0; c < NCHUNK; ++c) M = fmaxf(M, g_pm[b * NCHUNK + c]);

    float L = 0.f;
    float4 acc = make_float4(0.f, 0.f, 0.f, 0.f);
    #pragma unroll 8
    for (int c = 0; c < NCHUNK; ++c) {
        const int idx = b * NCHUNK + c;
        float wgt = __expf(g_pm[idx] - M);
        L += g_pl[idx] * wgt;
        float4 p = *reinterpret_cast<const float4*>(&g_pctx[(size_t)idx * Hdim + h4]);
        acc.x += wgt * p.x; acc.y += wgt * p.y; acc.z += wgt * p.z; acc.w += wgt * p.w;
    }
    float inv = 1.f / L;
    float4 o = make_float4(acc.x * inv, acc.y * inv, acc.z * inv, acc.w * inv);
    *reinterpret_cast<float4*>(&out[b * Hdim + h4]) = o;
}

// ---------------------------------------------------------------------------
extern "C" void kernel_launch(void* const* d_in, const int* in_sizes, int n_in,
                              void* d_out, int out_size) {
    const float* enc  = nullptr;   // 67108864
    const float* dec  = nullptr;   // 32768
    const void*  mask = nullptr;   // 65536
    const float* Wa   = nullptr;   // 1048576
    for (int i = 0; i < n_in; ++i) {
        switch (in_sizes[i]) {
            case 67108864: enc  = (const float*)d_in[i]; break;
            case 32768:    dec  = (const float*)d_in[i]; break;
            case 65536:    mask = d_in[i];               break;
            case 1048576:  Wa   = (const float*)d_in[i]; break;
        }
    }
    float* out = (float*)d_out;

    mask_detect<<<1, 1024>>>((const unsigned int*)mask);
    proj_kernel<<<Hdim, 256>>>(Wa, dec);
    dim3 grid(NCHUNK, Bdim);
    attn_main<<<grid, 256>>>(enc, mask);
    attn_reduce<<<dim3(Bdim, 4), 64>>>(out);
}

// round 4
// speedup vs baseline: 1.8243x; 1.6116x over previous
#include <cuda_runtime.h>

#define Bdim 32
#define Tdim 2048
#define Hdim 1024
#define Udim 1024
#define NCHUNK 32           // chunks per batch row
#define CHUNK 64            // Tdim / NCHUNK timesteps per CTA
#define NWARP 8
#define TPW (CHUNK / NWARP) // 8 timesteps per warp

// Scratch (no allocs allowed)
__device__ float g_v[Bdim * Hdim];                      // Wa @ dec
__device__ float g_pm[Bdim * NCHUNK];
__device__ float g_pl[Bdim * NCHUNK];
__device__ float g_pctx[(size_t)Bdim * NCHUNK * Hdim];  // 4 MB ctx partials
__device__ int   g_mode;                                // 0=int32 1=float32 2=uint8

// ---------------------------------------------------------------------------
// Kernel 0: detect mask storage format (writes g_mode only).
// ---------------------------------------------------------------------------
__global__ __launch_bounds__(1024) void mask_detect(const unsigned int* __restrict__ w) {
    __shared__ int s_not_int, s_not_flt;
    if (threadIdx.x == 0) { s_not_int = 0; s_not_flt = 0; }
    __syncthreads();
    int bad_i = 0, bad_f = 0;
    #pragma unroll 4
    for (int i = threadIdx.x; i < (Bdim * Tdim) / 4; i += 1024) {
        unsigned int x = w[i];
        if (x > 1u) bad_i = 1;
        if (x != 0u && x != 0x3f800000u) bad_f = 1;
    }
    if (bad_i) atomicOr(&s_not_int, 1);
    if (bad_f) atomicOr(&s_not_flt, 1);
    __syncthreads();
    if (threadIdx.x == 0)
        g_mode = (!s_not_int) ? 0 : ((!s_not_flt) ? 1 : 2);
}

// ---------------------------------------------------------------------------
// Kernel 1: v[b,h] = sum_u Wa[h,u] * dec_ht[b,u]
// ---------------------------------------------------------------------------
__global__ __launch_bounds__(256) void proj_kernel(const float* __restrict__ Wa,
                                                   const float* __restrict__ dec) {
    int h = blockIdx.x;
    __shared__ __align__(16) float w[Udim];
    for (int i = threadIdx.x; i < Udim; i += 256)
        w[i] = Wa[(size_t)h * Udim + i];
    __syncthreads();

    int warp = threadIdx.x >> 5;
    int lane = threadIdx.x & 31;
    for (int b = warp; b < Bdim; b += 8) {
        const float* d = dec + (size_t)b * Udim;
        float s = 0.f;
        #pragma unroll
        for (int k = 0; k < Udim / (32 * 4); ++k) {
            int u = (k * 32 + lane) * 4;
            float4 ww = *reinterpret_cast<const float4*>(&w[u]);
            float4 dd = *reinterpret_cast<const float4*>(&d[u]);
            s += ww.x * dd.x + ww.y * dd.y + ww.z * dd.z + ww.w * dd.w;
        }
        #pragma unroll
        for (int o = 16; o; o >>= 1) s += __shfl_xor_sync(0xffffffffu, s, o);
        if (lane == 0) g_v[b * Hdim + h] = s;
    }
}

// ---------------------------------------------------------------------------
// Kernel 2: warp-per-timestep fused pass with MASK SKIP — masked rows are
// never loaded (they contribute exactly 0: enc zeroed, exp(-1e9-m) == 0).
// No prefetch (reg pressure); occupancy 3 CTAs/SM for latency hiding.
// ---------------------------------------------------------------------------
__global__ __launch_bounds__(256, 3) void attn_main(const float* __restrict__ enc,
                                                    const void* __restrict__ mraw) {
    const int b    = blockIdx.y;
    const int c    = blockIdx.x;
    const int tid  = threadIdx.x;
    const int w    = tid >> 5;
    const int lane = tid & 31;

    __shared__ __align__(16) float sv[Hdim];          // 4 KB
    __shared__ __align__(16) float sctx[NWARP][Hdim]; // 32 KB
    __shared__ float sm[NWARP], sl[NWARP];

    for (int i = tid; i < Hdim; i += 256) sv[i] = g_v[b * Hdim + i];
    __syncthreads();

    const int mode  = g_mode;
    const int tbase = c * CHUNK + w * TPW;
    const float* rowp = enc + (size_t)b * Tdim * Hdim + (size_t)tbase * Hdim;
    const int mbase = b * Tdim + tbase;

    // Preload the 8 mask flags for this warp into a bitmask (front-batched).
    unsigned actbits = 0;
    #pragma unroll
    for (int j = 0; j < TPW; ++j) {
        bool a;
        if (mode == 0)      a = ((const int*)mraw)[mbase + j] != 0;
        else if (mode == 1) a = ((const float*)mraw)[mbase + j] != 0.f;
        else                a = ((const unsigned char*)mraw)[mbase + j] != 0;
        actbits |= (unsigned)a << j;
    }

    float4 ctx[8];
    #pragma unroll
    for (int k = 0; k < 8; ++k) ctx[k] = make_float4(0.f, 0.f, 0.f, 0.f);
    float m = -1e30f, l = 0.f;

    for (int j = 0; j < TPW; ++j) {
        if (!((actbits >> j) & 1u)) continue;   // masked row: contributes nothing

        const float* rp = rowp + (size_t)j * Hdim;
        float4 cur[8];
        #pragma unroll
        for (int k = 0; k < 8; ++k)
            cur[k] = *reinterpret_cast<const float4*>(rp + k * 128 + lane * 4);

        float s = 0.f;
        #pragma unroll
        for (int k = 0; k < 8; ++k) {
            float4 vv = *reinterpret_cast<const float4*>(&sv[k * 128 + lane * 4]);
            s += cur[k].x * vv.x + cur[k].y * vv.y + cur[k].z * vv.z + cur[k].w * vv.w;
        }
        #pragma unroll
        for (int o = 16; o; o >>= 1) s += __shfl_xor_sync(0xffffffffu, s, o);

        float mnew = fmaxf(m, s);
        if (mnew != m) {
            float scale = __expf(m - mnew);  // m=-1e30 first time -> 0 (l,ctx are 0)
            l *= scale;
            #pragma unroll
            for (int k = 0; k < 8; ++k) {
                ctx[k].x *= scale; ctx[k].y *= scale;
                ctx[k].z *= scale; ctx[k].w *= scale;
            }
            m = mnew;
        }
        float p = __expf(s - m);
        l += p;
        #pragma unroll
        for (int k = 0; k < 8; ++k) {
            ctx[k].x += p * cur[k].x; ctx[k].y += p * cur[k].y;
            ctx[k].z += p * cur[k].z; ctx[k].w += p * cur[k].w;
        }
    }

    // ---- merge 8 warps (exp(-1e30 - M) == 0 handles all-masked warps) ----
    if (lane == 0) { sm[w] = m; sl[w] = l; }
    #pragma unroll
    for (int k = 0; k < 8; ++k)
        *reinterpret_cast<float4*>(&sctx[w][k * 128 + lane * 4]) = ctx[k];
    __syncthreads();

    float M = -1e30f;
    #pragma unroll
    for (int ww = 0; ww < NWARP; ++ww) M = fmaxf(M, sm[ww]);
    float L = 0.f;
    float wsc[NWARP];
    #pragma unroll
    for (int ww = 0; ww < NWARP; ++ww) {
        wsc[ww] = __expf(sm[ww] - M);
        L += sl[ww] * wsc[ww];
    }

    const int h4 = tid * 4;
    float4 acc = make_float4(0.f, 0.f, 0.f, 0.f);
    #pragma unroll
    for (int ww = 0; ww < NWARP; ++ww) {
        float4 pc = *reinterpret_cast<const float4*>(&sctx[ww][h4]);
        acc.x += wsc[ww] * pc.x; acc.y += wsc[ww] * pc.y;
        acc.z += wsc[ww] * pc.z; acc.w += wsc[ww] * pc.w;
    }

    const int idx = b * NCHUNK + c;
    if (tid == 0) { g_pm[idx] = M; g_pl[idx] = L; }
    *reinterpret_cast<float4*>(&g_pctx[(size_t)idx * Hdim + h4]) = acc;
}

// ---------------------------------------------------------------------------
// Kernel 3: merge partials. Weights hoisted to smem FIRST so the main loop is
// a pure fully-unrolled LDG.128 + FFMA stream (high MLP, no MUFU in the path).
// ---------------------------------------------------------------------------
__global__ __launch_bounds__(256) void attn_reduce(float* __restrict__ out) {
    const int b   = blockIdx.x;
    const int tid = threadIdx.x;

    __shared__ float swgt[NCHUNK];
    __shared__ float sinv;

    if (tid < 32) {
        float pm = g_pm[b * NCHUNK + tid];
        float pl = g_pl[b * NCHUNK + tid];
        float M = pm;
        #pragma unroll
        for (int o = 16; o; o >>= 1) M = fmaxf(M, __shfl_xor_sync(0xffffffffu, M, o));
        float wg = __expf(pm - M);
        float Lc = wg * pl;
        #pragma unroll
        for (int o = 16; o; o >>= 1) Lc += __shfl_xor_sync(0xffffffffu, Lc, o);
        swgt[tid] = wg;
        if (tid == 0) sinv = (Lc > 0.f) ? 1.f / Lc : 0.f;   // guard all-masked row
    }
    __syncthreads();

    const float* base = g_pctx + (size_t)b * NCHUNK * Hdim + tid * 4;
    float4 acc = make_float4(0.f, 0.f, 0.f, 0.f);
    #pragma unroll
    for (int c = 0; c < NCHUNK; ++c) {
        float wg  = swgt[c];
        float4 p  = *reinterpret_cast<const float4*>(base + (size_t)c * Hdim);
        acc.x += wg * p.x; acc.y += wg * p.y; acc.z += wg * p.z; acc.w += wg * p.w;
    }
    float inv = sinv;
    float4 o = make_float4(acc.x * inv, acc.y * inv, acc.z * inv, acc.w * inv);
    *reinterpret_cast<float4*>(&out[b * Hdim + tid * 4]) = o;
}

// ---------------------------------------------------------------------------
extern "C" void kernel_launch(void* const* d_in, const int* in_sizes, int n_in,
                              void* d_out, int out_size) {
    const float* enc  = nullptr;   // 67108864
    const float* dec  = nullptr;   // 32768
    const void*  mask = nullptr;   // 65536
    const float* Wa   = nullptr;   // 1048576
    for (int i = 0; i < n_in; ++i) {
        switch (in_sizes[i]) {
            case 67108864: enc  = (const float*)d_in[i]; break;
            case 32768:    dec  = (const float*)d_in[i]; break;
            case 65536:    mask = d_in[i];               break;
            case 1048576:  Wa   = (const float*)d_in[i]; break;
        }
    }
    float* out = (float*)d_out;

    mask_detect<<<1, 1024>>>((const unsigned int*)mask);
    proj_kernel<<<Hdim, 256>>>(Wa, dec);
    dim3 grid(NCHUNK, Bdim);
    attn_main<<<grid, 256>>>(enc, mask);
    attn_reduce<<<Bdim, 256>>>(out);
}

// round 5
// speedup vs baseline: 2.2018x; 1.2070x over previous
#include <cuda_runtime.h>
#include <cstdint>

#define Bdim 32
#define Tdim 2048
#define Hdim 1024
#define Udim 1024
#define NCHUNK 32           // chunks per batch row
#define CHUNK 64            // timesteps per CTA
#define NWARP 4
#define TPW 16              // timesteps per warp
#define THREADS 128

// Scratch (no allocs allowed)
__device__ float g_v[Bdim * Hdim];
__device__ float g_pm[Bdim * NCHUNK];
__device__ float g_pl[Bdim * NCHUNK];
__device__ float g_pctx[(size_t)Bdim * NCHUNK * Hdim];  // 4 MB
__device__ int   g_mode;   // 0=int32 1=float32 2=uint8

__device__ __forceinline__ void cp16(uint32_t s, const float* g) {
    asm volatile("cp.async.cg.shared.global [%0], [%1], 16;" :: "r"(s), "l"(g));
}
#define CP_COMMIT() asm volatile("cp.async.commit_group;")
#define CP_WAIT0()  asm volatile("cp.async.wait_group 0;")
#define CP_WAIT1()  asm volatile("cp.async.wait_group 1;")

// ---------------------------------------------------------------------------
// Kernel 1: v[b,h] = sum_u Wa[h,u]*dec[b,u].  Block 0 additionally detects the
// mask storage format (runs in parallel with the other 1023 blocks' work).
// ---------------------------------------------------------------------------
__global__ __launch_bounds__(256) void proj_kernel(const float* __restrict__ Wa,
                                                   const float* __restrict__ dec,
                                                   const unsigned int* __restrict__ mw) {
    const int h = blockIdx.x;
    __shared__ __align__(16) float w[Udim];
    __shared__ int s_ni, s_nf;
    if (threadIdx.x == 0) { s_ni = 0; s_nf = 0; }
    for (int i = threadIdx.x; i < Udim; i += 256)
        w[i] = Wa[(size_t)h * Udim + i];
    __syncthreads();

    const int warp = threadIdx.x >> 5;
    const int lane = threadIdx.x & 31;
    for (int b = warp; b < Bdim; b += 8) {
        const float* d = dec + (size_t)b * Udim;
        float s = 0.f;
        #pragma unroll
        for (int k = 0; k < Udim / (32 * 4); ++k) {
            int u = (k * 32 + lane) * 4;
            float4 ww = *reinterpret_cast<const float4*>(&w[u]);
            float4 dd = *reinterpret_cast<const float4*>(&d[u]);
            s += ww.x * dd.x + ww.y * dd.y + ww.z * dd.z + ww.w * dd.w;
        }
        #pragma unroll
        for (int o = 16; o; o >>= 1) s += __shfl_xor_sync(0xffffffffu, s, o);
        if (lane == 0) g_v[b * Hdim + h] = s;
    }

    if (h == 0) {   // mask format sniff (block-uniform branch)
        int bi = 0, bf = 0;
        for (int i = threadIdx.x; i < (Bdim * Tdim) / 4; i += 256) {
            unsigned int x = mw[i];
            if (x > 1u) bi = 1;
            if (x != 0u && x != 0x3f800000u) bf = 1;
        }
        if (bi) atomicOr(&s_ni, 1);
        if (bf) atomicOr(&s_nf, 1);
        __syncthreads();
        if (threadIdx.x == 0)
            g_mode = (!s_ni) ? 0 : ((!s_nf) ? 1 : 2);
    }
}

// ---------------------------------------------------------------------------
// Kernel 2: warp-per-timestep fused pass, mask-skip, cp.async double-buffered
// row staging (load of next active row overlaps the full compute chain).
// Each warp owns up to TPW=16 rows; buffers are warp-private (no syncs).
// ---------------------------------------------------------------------------
__global__ __launch_bounds__(THREADS, 6) void attn_main(const float* __restrict__ enc,
                                                        const void* __restrict__ mraw) {
    const int b    = blockIdx.y;
    const int c    = blockIdx.x;
    const int tid  = threadIdx.x;
    const int w    = tid >> 5;
    const int lane = tid & 31;

    __shared__ __align__(16) float sv[Hdim];              // 4 KB
    __shared__ __align__(16) float sbuf[NWARP][2][Hdim];  // 32 KB (reused for merge)
    __shared__ float sm_[NWARP], sl_[NWARP];

    for (int i = tid; i < Hdim; i += THREADS) sv[i] = g_v[b * Hdim + i];
    __syncthreads();

    const int mode  = g_mode;
    const int tbase = c * CHUNK + w * TPW;
    const float* rowp = enc + (size_t)b * Tdim * Hdim + (size_t)tbase * Hdim;
    const int mbase = b * Tdim + tbase;

    // Active-row bitmask via ballot (lane j loads mask for row j).
    bool act = false;
    if (lane < TPW) {
        if (mode == 0)      act = ((const int*)mraw)[mbase + lane] != 0;
        else if (mode == 1) act = ((const float*)mraw)[mbase + lane] != 0.f;
        else                act = ((const unsigned char*)mraw)[mbase + lane] != 0;
    }
    unsigned rem = __ballot_sync(0xffffffffu, act) & ((1u << TPW) - 1u);

    float4 ctx[8];
    #pragma unroll
    for (int k = 0; k < 8; ++k) ctx[k] = make_float4(0.f, 0.f, 0.f, 0.f);
    float m = -1e30f, l = 0.f;

    const uint32_t sb0  = (uint32_t)__cvta_generic_to_shared(&sbuf[w][0][0]);
    const uint32_t sb1  = (uint32_t)__cvta_generic_to_shared(&sbuf[w][1][0]);
    const uint32_t loff = lane * 16;

    int jcur = -1;
    if (rem) {
        jcur = __ffs(rem) - 1; rem &= rem - 1;
        const float* gp = rowp + (size_t)jcur * Hdim;
        #pragma unroll
        for (int k = 0; k < 8; ++k) cp16(sb0 + k * 512 + loff, gp + k * 128 + lane * 4);
        CP_COMMIT();
    }
    int pb = 0;
    while (jcur >= 0) {
        int jn = -1;
        if (rem) {
            jn = __ffs(rem) - 1; rem &= rem - 1;
            const uint32_t dst = pb ? sb0 : sb1;
            const float* gp = rowp + (size_t)jn * Hdim;
            #pragma unroll
            for (int k = 0; k < 8; ++k) cp16(dst + k * 512 + loff, gp + k * 128 + lane * 4);
            CP_COMMIT();
            CP_WAIT1();      // oldest (current row) complete, next still in flight
        } else {
            CP_WAIT0();
        }

        const float* bufc = pb ? &sbuf[w][1][0] : &sbuf[w][0][0];

        float s = 0.f;
        #pragma unroll
        for (int k = 0; k < 8; ++k) {
            float4 cu = *reinterpret_cast<const float4*>(bufc + k * 128 + lane * 4);
            float4 vv = *reinterpret_cast<const float4*>(&sv[k * 128 + lane * 4]);
            s += cu.x * vv.x + cu.y * vv.y + cu.z * vv.z + cu.w * vv.w;
        }
        #pragma unroll
        for (int o = 16; o; o >>= 1) s += __shfl_xor_sync(0xffffffffu, s, o);

        float mnew = fmaxf(m, s);
        if (mnew != m) {
            float sc = __expf(m - mnew);   // first time: exp(-inf)=0, l/ctx are 0
            l *= sc;
            #pragma unroll
            for (int k = 0; k < 8; ++k) {
                ctx[k].x *= sc; ctx[k].y *= sc; ctx[k].z *= sc; ctx[k].w *= sc;
            }
            m = mnew;
        }
        float p = __expf(s - m);
        l += p;
        #pragma unroll
        for (int k = 0; k < 8; ++k) {
            float4 cu = *reinterpret_cast<const float4*>(bufc + k * 128 + lane * 4);
            ctx[k].x += p * cu.x; ctx[k].y += p * cu.y;
            ctx[k].z += p * cu.z; ctx[k].w += p * cu.w;
        }
        pb ^= 1;
        jcur = jn;
    }

    // ---- merge 4 warps (reuse sbuf[w][0] as per-warp ctx scratch) ----
    if (lane == 0) { sm_[w] = m; sl_[w] = l; }
    float* sctxw = &sbuf[w][0][0];
    #pragma unroll
    for (int k = 0; k < 8; ++k)
        *reinterpret_cast<float4*>(sctxw + k * 128 + lane * 4) = ctx[k];
    __syncthreads();

    float M = -1e30f;
    #pragma unroll
    for (int ww = 0; ww < NWARP; ++ww) M = fmaxf(M, sm_[ww]);
    float L = 0.f, wsc[NWARP];
    #pragma unroll
    for (int ww = 0; ww < NWARP; ++ww) {
        wsc[ww] = __expf(sm_[ww] - M);     // empty warp: exp(-1e30-M) -> 0
        L += sl_[ww] * wsc[ww];
    }

    const int idx = b * NCHUNK + c;
    #pragma unroll
    for (int half = 0; half < 2; ++half) {
        const int h4 = half * 512 + tid * 4;
        float4 acc = make_float4(0.f, 0.f, 0.f, 0.f);
        #pragma unroll
        for (int ww = 0; ww < NWARP; ++ww) {
            float4 pc = *reinterpret_cast<const float4*>(&sbuf[ww][0][h4]);
            acc.x += wsc[ww] * pc.x; acc.y += wsc[ww] * pc.y;
            acc.z += wsc[ww] * pc.z; acc.w += wsc[ww] * pc.w;
        }
        *reinterpret_cast<float4*>(&g_pctx[(size_t)idx * Hdim + h4]) = acc;
    }
    if (tid == 0) { g_pm[idx] = M; g_pl[idx] = L; }
}

// ---------------------------------------------------------------------------
// Kernel 3: merge partials. grid (Bdim, 8) x 32 threads = 256 CTAs so the
// 4 MB read builds real MLP; weights in smem, loop fully unrolled LDG.128+FFMA.
// ---------------------------------------------------------------------------
__global__ __launch_bounds__(32) void attn_reduce(float* __restrict__ out) {
    const int b    = blockIdx.x;
    const int lane = threadIdx.x;

    __shared__ float swgt[NCHUNK];
    __shared__ float sinv;

    float pm = g_pm[b * NCHUNK + lane];
    float pl = g_pl[b * NCHUNK + lane];
    float M = pm;
    #pragma unroll
    for (int o = 16; o; o >>= 1) M = fmaxf(M, __shfl_xor_sync(0xffffffffu, M, o));
    float wg = __expf(pm - M);
    float Lc = wg * pl;
    #pragma unroll
    for (int o = 16; o; o >>= 1) Lc += __shfl_xor_sync(0xffffffffu, Lc, o);
    swgt[lane] = wg;
    if (lane == 0) sinv = (Lc > 0.f) ? 1.f / Lc : 0.f;   // all-masked row -> 0
    __syncwarp();

    const int h4 = blockIdx.y * 128 + lane * 4;
    const float* base = g_pctx + (size_t)b * NCHUNK * Hdim + h4;
    float4 acc = make_float4(0.f, 0.f, 0.f, 0.f);
    #pragma unroll
    for (int c = 0; c < NCHUNK; ++c) {
        float wgc = swgt[c];
        float4 p = *reinterpret_cast<const float4*>(base + (size_t)c * Hdim);
        acc.x += wgc * p.x; acc.y += wgc * p.y;
        acc.z += wgc * p.z; acc.w += wgc * p.w;
    }
    float inv = sinv;
    float4 o = make_float4(acc.x * inv, acc.y * inv, acc.z * inv, acc.w * inv);
    *reinterpret_cast<float4*>(&out[b * Hdim + h4]) = o;
}

// ---------------------------------------------------------------------------
extern "C" void kernel_launch(void* const* d_in, const int* in_sizes, int n_in,
                              void* d_out, int out_size) {
    const float* enc  = nullptr;   // 67108864
    const float* dec  = nullptr;   // 32768
    const void*  mask = nullptr;   // 65536
    const float* Wa   = nullptr;   // 1048576
    for (int i = 0; i < n_in; ++i) {
        switch (in_sizes[i]) {
            case 67108864: enc  = (const float*)d_in[i]; break;
            case 32768:    dec  = (const float*)d_in[i]; break;
            case 65536:    mask = d_in[i];               break;
            case 1048576:  Wa   = (const float*)d_in[i]; break;
        }
    }
    float* out = (float*)d_out;

    proj_kernel<<<Hdim, 256>>>(Wa, dec, (const unsigned int*)mask);
    dim3 grid(NCHUNK, Bdim);
    attn_main<<<grid, THREADS>>>(enc, mask);
    attn_reduce<<<dim3(Bdim, 8), 32>>>(out);
}